// round 1
// baseline (speedup 1.0000x reference)
#include <cuda_runtime.h>

#define HDIM 2048
#define NTOK 8192          // B*S = 4*2048
#define NTHREADS 512
#define EPSV 1e-6f

__global__ __launch_bounds__(NTHREADS)
void altup_fused_kernel(const float* __restrict__ hs,     // [4, NTOK, H]
                        const float* __restrict__ act,    // [NTOK, H]
                        const float* __restrict__ w,      // [H] router_norm_weight
                        const float* __restrict__ rw,     // [4, H] modality_router_w
                        const float* __restrict__ pw,     // [16, 4] prediction_w
                        const float* __restrict__ cw,     // [4, 4] correction_w
                        const float* __restrict__ oscale, // [H]
                        float* __restrict__ out)          // [4, NTOK, H]
{
    const int t   = blockIdx.x;
    const int tid = threadIdx.x;
    const int h4  = tid * 4;

    const float* hs0 = hs  + (size_t)t * HDIM;
    const float* at  = act + (size_t)t * HDIM;

    // ---- Phase 1: streaming loads for the two router reductions ----
    float4 x0 = *(const float4*)(hs0 + h4);
    float4 av = *(const float4*)(at  + h4);
    float4 wv = *(const float4*)(w   + h4);
    float4 r0 = *(const float4*)(rw + 0*HDIM + h4);
    float4 r1 = *(const float4*)(rw + 1*HDIM + h4);
    float4 r2 = *(const float4*)(rw + 2*HDIM + h4);
    float4 r3 = *(const float4*)(rw + 3*HDIM + h4);

    float p[10];
    {
        float4 xw = make_float4(x0.x*wv.x, x0.y*wv.y, x0.z*wv.z, x0.w*wv.w);
        float4 aw = make_float4(av.x*wv.x, av.y*wv.y, av.z*wv.z, av.w*wv.w);
        p[0] = x0.x*x0.x + x0.y*x0.y + x0.z*x0.z + x0.w*x0.w;
        p[1] = xw.x*r0.x + xw.y*r0.y + xw.z*r0.z + xw.w*r0.w;
        p[2] = xw.x*r1.x + xw.y*r1.y + xw.z*r1.z + xw.w*r1.w;
        p[3] = xw.x*r2.x + xw.y*r2.y + xw.z*r2.z + xw.w*r2.w;
        p[4] = xw.x*r3.x + xw.y*r3.y + xw.z*r3.z + xw.w*r3.w;
        p[5] = av.x*av.x + av.y*av.y + av.z*av.z + av.w*av.w;
        p[6] = aw.x*r0.x + aw.y*r0.y + aw.z*r0.z + aw.w*r0.w;
        p[7] = aw.x*r1.x + aw.y*r1.y + aw.z*r1.z + aw.w*r1.w;
        p[8] = aw.x*r2.x + aw.y*r2.y + aw.z*r2.z + aw.w*r2.w;
        p[9] = aw.x*r3.x + aw.y*r3.y + aw.z*r3.z + aw.w*r3.w;
    }

    // ---- block reduce 10 values ----
    __shared__ float red[16][10];
    __shared__ float fin[10];
    #pragma unroll
    for (int k = 0; k < 10; k++) {
        #pragma unroll
        for (int o = 16; o > 0; o >>= 1)
            p[k] += __shfl_xor_sync(0xffffffffu, p[k], o);
    }
    const int warp = tid >> 5, lane = tid & 31;
    if (lane == 0) {
        #pragma unroll
        for (int k = 0; k < 10; k++) red[warp][k] = p[k];
    }
    __syncthreads();
    if (tid < 10) {
        float s = 0.f;
        #pragma unroll
        for (int wi = 0; wi < 16; wi++) s += red[wi][tid];
        fin[tid] = s;
    }
    __syncthreads();

    // ---- tiny per-token coefficient math (redundant across threads) ----
    const float inv_h = 1.0f / (float)HDIM;
    float g0 = rsqrtf(fin[0] * inv_h + EPSV) * inv_h;   // rms(x0) * router_input_scale
    float g1 = rsqrtf(fin[5] * inv_h + EPSV) * inv_h;   // rms(act) * router_input_scale
    float m0[4], m1[4];
    #pragma unroll
    for (int n = 0; n < 4; n++) {
        m0[n] = tanhf(fin[1 + n] * g0);
        m1[n] = tanhf(fin[6 + n] * g1);
    }
    float c[4][4];
    #pragma unroll
    for (int j = 0; j < 4; j++)
        #pragma unroll
        for (int i = 0; i < 4; i++) {
            float s = 0.f;
            #pragma unroll
            for (int n = 0; n < 4; n++) s += m0[n] * __ldg(&pw[(j*4 + i)*4 + n]);
            c[j][i] = s;
        }
    float cc[4];
    #pragma unroll
    for (int n = 0; n < 4; n++) {
        float s = 1.0f;
        #pragma unroll
        for (int k = 0; k < 4; k++) s += m1[k] * __ldg(&cw[n*4 + k]);
        cc[n] = s;
    }

    // ---- Phase 2: remaining streams + elementwise combine ----
    float4 xv[4];
    xv[0] = x0;
    xv[1] = *(const float4*)(hs + ((size_t)1*NTOK + t)*HDIM + h4);
    xv[2] = *(const float4*)(hs + ((size_t)2*NTOK + t)*HDIM + h4);
    xv[3] = *(const float4*)(hs + ((size_t)3*NTOK + t)*HDIM + h4);
    float4 sv = *(const float4*)(oscale + h4);

    float xc[4][4];     // [stream i][component]
    #pragma unroll
    for (int i = 0; i < 4; i++) {
        xc[i][0] = xv[i].x; xc[i][1] = xv[i].y; xc[i][2] = xv[i].z; xc[i][3] = xv[i].w;
    }
    const float ac[4] = {av.x, av.y, av.z, av.w};
    const float sc[4] = {sv.x, sv.y, sv.z, sv.w};

    float ov[4][4];     // [n][component]
    #pragma unroll
    for (int comp = 0; comp < 4; comp++) {
        float pred[4];
        #pragma unroll
        for (int j = 0; j < 4; j++) {
            float s = xc[j][comp];
            #pragma unroll
            for (int i = 0; i < 4; i++) s += c[j][i] * xc[i][comp];
            pred[j] = s;
        }
        float innov = ac[comp] - pred[0];
        #pragma unroll
        for (int n = 0; n < 4; n++)
            ov[n][comp] = (pred[n] + innov * cc[n]) * sc[comp];
    }

    #pragma unroll
    for (int n = 0; n < 4; n++) {
        *(float4*)(out + ((size_t)n*NTOK + t)*HDIM + h4) =
            make_float4(ov[n][0], ov[n][1], ov[n][2], ov[n][3]);
    }
}

extern "C" void kernel_launch(void* const* d_in, const int* in_sizes, int n_in,
                              void* d_out, int out_size)
{
    const float* hs     = (const float*)d_in[0];  // [4,4,2048,2048]
    const float* act    = (const float*)d_in[1];  // [4,2048,2048]
    const float* w      = (const float*)d_in[2];  // [2048]
    const float* rw     = (const float*)d_in[3];  // [4,2048]
    const float* pw     = (const float*)d_in[4];  // [16,4]
    const float* cw     = (const float*)d_in[5];  // [4,4]
    const float* oscale = (const float*)d_in[6];  // [2048]
    float* out = (float*)d_out;

    altup_fused_kernel<<<NTOK, NTHREADS>>>(hs, act, w, rw, pw, cw, oscale, out);
}

// round 2
// speedup vs baseline: 1.0388x; 1.0388x over previous
#include <cuda_runtime.h>

#define HDIM 2048
#define NTOK 8192          // B*S = 4*2048
#define NTHREADS 512
#define EPSV 1e-6f

// pinned-order streaming 128-bit load (evict-first: read-once data)
__device__ __forceinline__ float4 ldcs4(const float* p) {
    float4 v;
    asm volatile("ld.global.cs.v4.f32 {%0,%1,%2,%3}, [%4];"
                 : "=f"(v.x), "=f"(v.y), "=f"(v.z), "=f"(v.w) : "l"(p));
    return v;
}
__device__ __forceinline__ void stcs4(float* p, float4 v) {
    asm volatile("st.global.cs.v4.f32 [%0], {%1,%2,%3,%4};"
                 :: "l"(p), "f"(v.x), "f"(v.y), "f"(v.z), "f"(v.w));
}

__global__ __launch_bounds__(NTHREADS, 2)
void altup_fused_kernel(const float* __restrict__ hs,     // [4, NTOK, H]
                        const float* __restrict__ act,    // [NTOK, H]
                        const float* __restrict__ w,      // [H]
                        const float* __restrict__ rw,     // [4, H]
                        const float* __restrict__ pw,     // [16, 4]
                        const float* __restrict__ cw,     // [4, 4]
                        const float* __restrict__ oscale, // [H]
                        float* __restrict__ out)          // [4, NTOK, H]
{
    const int t   = blockIdx.x;
    const int tid = threadIdx.x;
    const int h4  = tid * 4;

    // ---- Phase 1: reduction-input streams + cached weights ----
    float4 x0 = ldcs4(hs  + (size_t)t * HDIM + h4);
    float4 av = ldcs4(act + (size_t)t * HDIM + h4);
    float4 wv = *(const float4*)(w   + h4);
    float4 r0 = *(const float4*)(rw + 0*HDIM + h4);
    float4 r1 = *(const float4*)(rw + 1*HDIM + h4);
    float4 r2 = *(const float4*)(rw + 2*HDIM + h4);
    float4 r3 = *(const float4*)(rw + 3*HDIM + h4);

    float p[10];
    {
        float4 xw = make_float4(x0.x*wv.x, x0.y*wv.y, x0.z*wv.z, x0.w*wv.w);
        float4 aw = make_float4(av.x*wv.x, av.y*wv.y, av.z*wv.z, av.w*wv.w);
        p[0] = x0.x*x0.x + x0.y*x0.y + x0.z*x0.z + x0.w*x0.w;
        p[1] = xw.x*r0.x + xw.y*r0.y + xw.z*r0.z + xw.w*r0.w;
        p[2] = xw.x*r1.x + xw.y*r1.y + xw.z*r1.z + xw.w*r1.w;
        p[3] = xw.x*r2.x + xw.y*r2.y + xw.z*r2.z + xw.w*r2.w;
        p[4] = xw.x*r3.x + xw.y*r3.y + xw.z*r3.z + xw.w*r3.w;
        p[5] = av.x*av.x + av.y*av.y + av.z*av.z + av.w*av.w;
        p[6] = aw.x*r0.x + aw.y*r0.y + aw.z*r0.z + aw.w*r0.w;
        p[7] = aw.x*r1.x + aw.y*r1.y + aw.z*r1.z + aw.w*r1.w;
        p[8] = aw.x*r2.x + aw.y*r2.y + aw.z*r2.z + aw.w*r2.w;
        p[9] = aw.x*r3.x + aw.y*r3.y + aw.z*r3.z + aw.w*r3.w;
    }

    // ---- Prefetch Phase-2 streams NOW (weights dead, regs free).
    // asm volatile pins these LDGs before the reduction so their DRAM
    // latency overlaps the shuffle/smem reduce + barriers.
    float4 x1 = ldcs4(hs + ((size_t)1*NTOK + t)*HDIM + h4);
    float4 x2 = ldcs4(hs + ((size_t)2*NTOK + t)*HDIM + h4);
    float4 x3 = ldcs4(hs + ((size_t)3*NTOK + t)*HDIM + h4);
    float4 sv = *(const float4*)(oscale + h4);

    // ---- block reduce 10 values ----
    __shared__ float red[16][10];
    __shared__ float fin[10];
    #pragma unroll
    for (int k = 0; k < 10; k++) {
        #pragma unroll
        for (int o = 16; o > 0; o >>= 1)
            p[k] += __shfl_xor_sync(0xffffffffu, p[k], o);
    }
    const int warp = tid >> 5, lane = tid & 31;
    if (lane == 0) {
        #pragma unroll
        for (int k = 0; k < 10; k++) red[warp][k] = p[k];
    }
    __syncthreads();
    if (tid < 10) {
        float s = 0.f;
        #pragma unroll
        for (int wi = 0; wi < 16; wi++) s += red[wi][tid];
        fin[tid] = s;
    }
    __syncthreads();

    // ---- tiny per-token coefficient math (redundant across threads) ----
    const float inv_h = 1.0f / (float)HDIM;
    float g0 = rsqrtf(fin[0] * inv_h + EPSV) * inv_h;
    float g1 = rsqrtf(fin[5] * inv_h + EPSV) * inv_h;
    float m0[4], m1[4];
    #pragma unroll
    for (int n = 0; n < 4; n++) {
        m0[n] = tanhf(fin[1 + n] * g0);
        m1[n] = tanhf(fin[6 + n] * g1);
    }
    float c[4][4];
    #pragma unroll
    for (int j = 0; j < 4; j++)
        #pragma unroll
        for (int i = 0; i < 4; i++) {
            float s = 0.f;
            #pragma unroll
            for (int n = 0; n < 4; n++) s += m0[n] * __ldg(&pw[(j*4 + i)*4 + n]);
            c[j][i] = s;
        }
    float cc[4];
    #pragma unroll
    for (int n = 0; n < 4; n++) {
        float s = 1.0f;
        #pragma unroll
        for (int k = 0; k < 4; k++) s += m1[k] * __ldg(&cw[n*4 + k]);
        cc[n] = s;
    }

    // ---- Phase 2: elementwise combine (data already in regs) ----
    float xc[4][4];
    xc[0][0]=x0.x; xc[0][1]=x0.y; xc[0][2]=x0.z; xc[0][3]=x0.w;
    xc[1][0]=x1.x; xc[1][1]=x1.y; xc[1][2]=x1.z; xc[1][3]=x1.w;
    xc[2][0]=x2.x; xc[2][1]=x2.y; xc[2][2]=x2.z; xc[2][3]=x2.w;
    xc[3][0]=x3.x; xc[3][1]=x3.y; xc[3][2]=x3.z; xc[3][3]=x3.w;
    const float ac[4] = {av.x, av.y, av.z, av.w};
    const float sc[4] = {sv.x, sv.y, sv.z, sv.w};

    float ov[4][4];
    #pragma unroll
    for (int comp = 0; comp < 4; comp++) {
        float pred[4];
        #pragma unroll
        for (int j = 0; j < 4; j++) {
            float s = xc[j][comp];
            #pragma unroll
            for (int i = 0; i < 4; i++) s += c[j][i] * xc[i][comp];
            pred[j] = s;
        }
        float innov = ac[comp] - pred[0];
        #pragma unroll
        for (int n = 0; n < 4; n++)
            ov[n][comp] = (pred[n] + innov * cc[n]) * sc[comp];
    }

    #pragma unroll
    for (int n = 0; n < 4; n++) {
        stcs4(out + ((size_t)n*NTOK + t)*HDIM + h4,
              make_float4(ov[n][0], ov[n][1], ov[n][2], ov[n][3]));
    }
}

extern "C" void kernel_launch(void* const* d_in, const int* in_sizes, int n_in,
                              void* d_out, int out_size)
{
    const float* hs     = (const float*)d_in[0];
    const float* act    = (const float*)d_in[1];
    const float* w      = (const float*)d_in[2];
    const float* rw     = (const float*)d_in[3];
    const float* pw     = (const float*)d_in[4];
    const float* cw     = (const float*)d_in[5];
    const float* oscale = (const float*)d_in[6];
    float* out = (float*)d_out;

    altup_fused_kernel<<<NTOK, NTHREADS>>>(hs, act, w, rw, pw, cw, oscale, out);
}

// round 3
// speedup vs baseline: 1.1020x; 1.0608x over previous
#include <cuda_runtime.h>

#define HDIM 2048
#define NTOK 8192          // B*S = 4*2048
#define NTHREADS 512
#define EPSV 1e-6f

__device__ __forceinline__ float4 ldcs4(const float* p) {
    float4 v;
    asm volatile("ld.global.cs.v4.f32 {%0,%1,%2,%3}, [%4];"
                 : "=f"(v.x), "=f"(v.y), "=f"(v.z), "=f"(v.w) : "l"(p));
    return v;
}
__device__ __forceinline__ void stcs4(float* p, float4 v) {
    asm volatile("st.global.cs.v4.f32 [%0], {%1,%2,%3,%4};"
                 :: "l"(p), "f"(v.x), "f"(v.y), "f"(v.z), "f"(v.w));
}

__device__ __forceinline__ float dot4(float4 a, float4 b) {
    return a.x*b.x + a.y*b.y + a.z*b.z + a.w*b.w;
}

// Build 4x4 prediction coefs + 4 correction coefs from the 10 reduced sums
// of one token (smem broadcast reads).
__device__ __forceinline__ void make_coefs(const volatile float* fin,
                                           const float* __restrict__ pw,
                                           const float* __restrict__ cw,
                                           float c[4][4], float cc[4])
{
    const float inv_h = 1.0f / (float)HDIM;
    float g0 = rsqrtf(fin[0] * inv_h + EPSV) * inv_h;
    float g1 = rsqrtf(fin[5] * inv_h + EPSV) * inv_h;
    float m0[4], m1[4];
    #pragma unroll
    for (int n = 0; n < 4; n++) {
        m0[n] = tanhf(fin[1 + n] * g0);
        m1[n] = tanhf(fin[6 + n] * g1);
    }
    #pragma unroll
    for (int j = 0; j < 4; j++)
        #pragma unroll
        for (int i = 0; i < 4; i++) {
            float s = 0.f;
            #pragma unroll
            for (int n = 0; n < 4; n++) s += m0[n] * __ldg(&pw[(j*4 + i)*4 + n]);
            c[j][i] = s;
        }
    #pragma unroll
    for (int n = 0; n < 4; n++) {
        float s = 1.0f;
        #pragma unroll
        for (int k = 0; k < 4; k++) s += m1[k] * __ldg(&cw[n*4 + k]);
        cc[n] = s;
    }
}

// Elementwise predict+correct+scale for one token (all data in regs), 4 stores.
__device__ __forceinline__ void phase2(const float4 xv0, const float4 xv1,
                                       const float4 xv2, const float4 xv3,
                                       const float4 av, const float4 sv,
                                       const float c[4][4], const float cc[4],
                                       float* __restrict__ out, int t, int h4)
{
    float xc[4][4];
    xc[0][0]=xv0.x; xc[0][1]=xv0.y; xc[0][2]=xv0.z; xc[0][3]=xv0.w;
    xc[1][0]=xv1.x; xc[1][1]=xv1.y; xc[1][2]=xv1.z; xc[1][3]=xv1.w;
    xc[2][0]=xv2.x; xc[2][1]=xv2.y; xc[2][2]=xv2.z; xc[2][3]=xv2.w;
    xc[3][0]=xv3.x; xc[3][1]=xv3.y; xc[3][2]=xv3.z; xc[3][3]=xv3.w;
    const float ac[4] = {av.x, av.y, av.z, av.w};
    const float sc[4] = {sv.x, sv.y, sv.z, sv.w};

    float ov[4][4];
    #pragma unroll
    for (int comp = 0; comp < 4; comp++) {
        float pred[4];
        #pragma unroll
        for (int j = 0; j < 4; j++) {
            float s = xc[j][comp];
            #pragma unroll
            for (int i = 0; i < 4; i++) s += c[j][i] * xc[i][comp];
            pred[j] = s;
        }
        float innov = ac[comp] - pred[0];
        #pragma unroll
        for (int n = 0; n < 4; n++)
            ov[n][comp] = (pred[n] + innov * cc[n]) * sc[comp];
    }
    #pragma unroll
    for (int n = 0; n < 4; n++)
        stcs4(out + ((size_t)n*NTOK + t)*HDIM + h4,
              make_float4(ov[n][0], ov[n][1], ov[n][2], ov[n][3]));
}

__global__ __launch_bounds__(NTHREADS, 2)
void altup_fused2_kernel(const float* __restrict__ hs,     // [4, NTOK, H]
                         const float* __restrict__ act,    // [NTOK, H]
                         const float* __restrict__ w,      // [H]
                         const float* __restrict__ rw,     // [4, H]
                         const float* __restrict__ pw,     // [16, 4]
                         const float* __restrict__ cw,     // [4, 4]
                         const float* __restrict__ oscale, // [H]
                         float* __restrict__ out)          // [4, NTOK, H]
{
    const int t0  = blockIdx.x * 2;
    const int t1  = t0 + 1;
    const int tid = threadIdx.x;
    const int h4  = tid * 4;

    // ---- reduction-input streams for both tokens ----
    float4 x0a = ldcs4(hs  + (size_t)t0 * HDIM + h4);
    float4 ava = ldcs4(act + (size_t)t0 * HDIM + h4);
    float4 x0b = ldcs4(hs  + (size_t)t1 * HDIM + h4);
    float4 avb = ldcs4(act + (size_t)t1 * HDIM + h4);

    // ---- weights (cached, reused by both tokens) ----
    float4 wv = *(const float4*)(w   + h4);
    float4 r0 = *(const float4*)(rw + 0*HDIM + h4);
    float4 r1 = *(const float4*)(rw + 1*HDIM + h4);
    float4 r2 = *(const float4*)(rw + 2*HDIM + h4);
    float4 r3 = *(const float4*)(rw + 3*HDIM + h4);

    float p[20];
    {
        float4 xwa = make_float4(x0a.x*wv.x, x0a.y*wv.y, x0a.z*wv.z, x0a.w*wv.w);
        float4 awa = make_float4(ava.x*wv.x, ava.y*wv.y, ava.z*wv.z, ava.w*wv.w);
        float4 xwb = make_float4(x0b.x*wv.x, x0b.y*wv.y, x0b.z*wv.z, x0b.w*wv.w);
        float4 awb = make_float4(avb.x*wv.x, avb.y*wv.y, avb.z*wv.z, avb.w*wv.w);
        p[0] = dot4(x0a, x0a);
        p[1] = dot4(xwa, r0);  p[2] = dot4(xwa, r1);
        p[3] = dot4(xwa, r2);  p[4] = dot4(xwa, r3);
        p[5] = dot4(ava, ava);
        p[6] = dot4(awa, r0);  p[7] = dot4(awa, r1);
        p[8] = dot4(awa, r2);  p[9] = dot4(awa, r3);
        p[10] = dot4(x0b, x0b);
        p[11] = dot4(xwb, r0); p[12] = dot4(xwb, r1);
        p[13] = dot4(xwb, r2); p[14] = dot4(xwb, r3);
        p[15] = dot4(avb, avb);
        p[16] = dot4(awb, r0); p[17] = dot4(awb, r1);
        p[18] = dot4(awb, r2); p[19] = dot4(awb, r3);
    }

    // ---- prefetch token-A phase-2 streams + scale (weights now dead) ----
    float4 sv  = *(const float4*)(oscale + h4);
    float4 x1a = ldcs4(hs + ((size_t)1*NTOK + t0)*HDIM + h4);
    float4 x2a = ldcs4(hs + ((size_t)2*NTOK + t0)*HDIM + h4);
    float4 x3a = ldcs4(hs + ((size_t)3*NTOK + t0)*HDIM + h4);

    // ---- block reduce 20 values ----
    __shared__ float red[16][20];
    __shared__ float fin[20];
    #pragma unroll
    for (int k = 0; k < 20; k++) {
        #pragma unroll
        for (int o = 16; o > 0; o >>= 1)
            p[k] += __shfl_xor_sync(0xffffffffu, p[k], o);
    }
    const int warp = tid >> 5, lane = tid & 31;
    if (lane == 0) {
        #pragma unroll
        for (int k = 0; k < 20; k++) red[warp][k] = p[k];
    }
    __syncthreads();
    if (tid < 20) {
        float s = 0.f;
        #pragma unroll
        for (int wi = 0; wi < 16; wi++) s += red[wi][tid];
        fin[tid] = s;
    }
    __syncthreads();

    // ---- issue token-B phase-2 loads early (latency hides under A's math) ----
    float4 x1b = ldcs4(hs + ((size_t)1*NTOK + t1)*HDIM + h4);
    float4 x2b = ldcs4(hs + ((size_t)2*NTOK + t1)*HDIM + h4);
    float4 x3b = ldcs4(hs + ((size_t)3*NTOK + t1)*HDIM + h4);

    // ---- token A: coefs + elementwise ----
    {
        float c[4][4], cc[4];
        make_coefs(fin, pw, cw, c, cc);
        phase2(x0a, x1a, x2a, x3a, ava, sv, c, cc, out, t0, h4);
    }
    // ---- token B ----
    {
        float c[4][4], cc[4];
        make_coefs(fin + 10, pw, cw, c, cc);
        phase2(x0b, x1b, x2b, x3b, avb, sv, c, cc, out, t1, h4);
    }
}

extern "C" void kernel_launch(void* const* d_in, const int* in_sizes, int n_in,
                              void* d_out, int out_size)
{
    const float* hs     = (const float*)d_in[0];
    const float* act    = (const float*)d_in[1];
    const float* w      = (const float*)d_in[2];
    const float* rw     = (const float*)d_in[3];
    const float* pw     = (const float*)d_in[4];
    const float* cw     = (const float*)d_in[5];
    const float* oscale = (const float*)d_in[6];
    float* out = (float*)d_out;

    altup_fused2_kernel<<<NTOK/2, NTHREADS>>>(hs, act, w, rw, pw, cw, oscale, out);
}